// round 3
// baseline (speedup 1.0000x reference)
#include <cuda_runtime.h>
#include <math.h>

// ---------------- static config ----------------
constexpr int NXg = 432, NYg = 496, Bb = 4;
constexpr int Hh = 248, Ww = 216;
constexpr int HW = Hh * Ww;            // 53568
constexpr int C_IN = 384, NDF = 16;
constexpr int NYNX = NYg * NXg;        // 214272
constexpr int KS = 15, RR = 7;
constexpr float BN_EPS = 1e-3f;
constexpr int CNT = Bb * HW;           // 214272
constexpr int PL4 = HW / 4;            // 13392

// tiled grids: 16x16 pixel tiles over (H=248, W=216) -> 16 x 14 tiles
constexpr int TW = 14, TH = 16;
constexpr int NB1 = TW * TH * Bb;      // 896 blocks

// ---------------- scratch (static, no allocation) ----------------
__device__ int   d_hist[Bb * NYNX];
__device__ float d_dm  [Bb * NYNX];
__device__ int   d_max [Bb];
__device__ float d_gauss[KS];
__device__ float d_buf1[Bb * 8  * HW];
__device__ float d_buf2[Bb * 16 * HW];
__device__ float d_part1[16 * NB1];
__device__ float d_part2[32 * NB1];
__device__ float d_sc1[8],  d_sh1[8];
__device__ float d_sc2[16], d_sh2[16];

// ---------------- kernels ----------------
__global__ void k_init() {
    int i = blockIdx.x * blockDim.x + threadIdx.x;
    int stride = gridDim.x * blockDim.x;
    for (int p = i; p < Bb * NYNX; p += stride) d_hist[p] = 0;
    if (i < Bb) d_max[i] = 0;
    if (i == 0) {
        float g[KS]; float s = 0.f;
        #pragma unroll
        for (int k = 0; k < KS; k++) {
            float c = (float)(k - RR);
            g[k] = expf(-(c * c) / 78.125f);   // 2*sigma^2, sigma=6.25
            s += g[k];
        }
        #pragma unroll
        for (int k = 0; k < KS; k++) d_gauss[k] = g[k] / s;
    }
}

__global__ void k_hist(const float* __restrict__ pts, int n) {
    int i = blockIdx.x * blockDim.x + threadIdx.x;
    if (i >= n) return;
    float b_f = pts[i * 5 + 0];
    float px  = pts[i * 5 + 1];
    float py  = pts[i * 5 + 2];
    int b  = (int)b_f;
    int xi = (int)__fdiv_rn(px - 0.0f, 0.16f);      // exact f32 division semantics
    int yi = (int)__fdiv_rn(py - (-39.68f), 0.16f);
    xi = min(max(xi, 0), NXg - 1);
    yi = min(max(yi, 0), NYg - 1);
    atomicAdd(&d_hist[b * NYNX + yi * NXg + xi], 1);
}

// fused separable 15-tap gaussian blur (zero pad) + per-batch max
// tile 32x32 out, halo 7
__global__ __launch_bounds__(256) void k_blur() {
    __shared__ float a[46][48];
    __shared__ float v[32][48];
    __shared__ float g[KS];
    __shared__ float red[256];
    int b = blockIdx.z;
    int x0 = blockIdx.x * 32, y0 = blockIdx.y * 32;
    int tid = threadIdx.x;
    if (tid < KS) g[tid] = d_gauss[tid];
    const int* h = d_hist + b * NYNX;
    for (int i = tid; i < 46 * 46; i += 256) {
        int ly = i / 46, lx = i - ly * 46;
        int gy = y0 - 7 + ly, gx = x0 - 7 + lx;
        a[ly][lx] = (gy >= 0 && gy < NYg && gx >= 0 && gx < NXg)
                        ? (float)h[gy * NXg + gx] : 0.f;
    }
    __syncthreads();
    // vertical pass: rows 0..31 of output space, cols 0..45 (incl. x halo)
    for (int i = tid; i < 32 * 46; i += 256) {
        int ly = i / 46, lx = i - ly * 46;
        float acc = 0.f;
        #pragma unroll
        for (int j = 0; j < KS; j++) acc = fmaf(g[j], a[ly + j][lx], acc);
        v[ly][lx] = acc;
    }
    __syncthreads();
    // horizontal pass + write + max
    float m = 0.f;
    for (int i = tid; i < 32 * 32; i += 256) {
        int ly = i / 32, lx = i - ly * 32;
        int gy = y0 + ly, gx = x0 + lx;
        if (gy < NYg && gx < NXg) {
            float acc = 0.f;
            #pragma unroll
            for (int j = 0; j < KS; j++) acc = fmaf(g[j], v[ly][lx + j], acc);
            d_dm[b * NYNX + gy * NXg + gx] = acc;
            m = fmaxf(m, acc);
        }
    }
    red[tid] = m;
    __syncthreads();
    for (int s = 128; s > 0; s >>= 1) {
        if (tid < s) red[tid] = fmaxf(red[tid], red[tid + s]);
        __syncthreads();
    }
    if (tid == 0) atomicMax(&d_max[b], __float_as_int(red[0]));  // vals >= 0
}

// fused: antialiased 2x resize (+ /max) -> conv3x3 1->8 -> BN1 partial stats
// 16x16 output tile per block; resized halo 18x18; dm region 38x38
__global__ __launch_bounds__(256) void k_resconv1(const float* __restrict__ w1) {
    __shared__ float dms[38][40];
    __shared__ float rs[18][20];
    __shared__ float sw[72];
    __shared__ float wred[16 * 8];
    int b = blockIdx.z;
    int x0 = blockIdx.x * 16, y0 = blockIdx.y * 16;
    int tid = threadIdx.x;
    if (tid < 72) sw[tid] = w1[tid];
    const float* dm = d_dm + b * NYNX;
    int gy0 = 2 * y0 - 3, gx0 = 2 * x0 - 3;
    for (int i = tid; i < 38 * 38; i += 256) {
        int ly = i / 38, lx = i - ly * 38;
        int gy = gy0 + ly, gx = gx0 + lx;
        dms[ly][lx] = (gy >= 0 && gy < NYg && gx >= 0 && gx < NXg)
                          ? dm[gy * NXg + gx] : 0.f;
    }
    __syncthreads();
    float mx = __int_as_float(d_max[b]);
    float inv_mx = (mx > 0.f) ? (1.f / mx) : 1.f;
    // resized values (raw weights 0.25/0.75, edge-renormalized)
    for (int i = tid; i < 18 * 18; i += 256) {
        int ly = i / 18, lx = i - ly * 18;
        int yr = y0 - 1 + ly, xr = x0 - 1 + lx;
        float wy[4], wx[4]; int ry[4], rx[4];
        float sy = 0.f, sx = 0.f;
        #pragma unroll
        for (int j = 0; j < 4; j++) {
            float w = (j == 0 || j == 3) ? 0.25f : 0.75f;
            int r = 2 * yr - 1 + j;
            bool vr = (r >= 0) && (r < NYg);
            wy[j] = vr ? w : 0.f; ry[j] = vr ? (r - gy0) : 0; sy += wy[j];
            int c = 2 * xr - 1 + j;
            bool vc = (c >= 0) && (c < NXg);
            wx[j] = vc ? w : 0.f; rx[j] = vc ? (c - gx0) : 0; sx += wx[j];
        }
        #pragma unroll
        for (int j = 0; j < 4; j++) { wy[j] /= sy; wx[j] /= sx; }
        float acc = 0.f;
        #pragma unroll
        for (int jy = 0; jy < 4; jy++) {
            float r = 0.f;
            #pragma unroll
            for (int jx = 0; jx < 4; jx++) r = fmaf(wx[jx], dms[ry[jy]][rx[jx]], r);
            acc = fmaf(wy[jy], r, acc);
        }
        rs[ly][lx] = acc * inv_mx;
    }
    __syncthreads();
    // conv3x3 1->8, zero pad at image edges
    int ty = tid >> 4, tx = tid & 15;
    int y = y0 + ty, x = x0 + tx;
    float acc[8] = {0.f,0.f,0.f,0.f,0.f,0.f,0.f,0.f};
    if (y < Hh && x < Ww) {
        #pragma unroll
        for (int ky = 0; ky < 3; ky++) {
            int yy = y + ky - 1;
            if (yy < 0 || yy >= Hh) continue;
            #pragma unroll
            for (int kx = 0; kx < 3; kx++) {
                int xx = x + kx - 1;
                if (xx < 0 || xx >= Ww) continue;
                float vv = rs[ty + ky][tx + kx];
                int wi = ky * 3 + kx;
                #pragma unroll
                for (int c = 0; c < 8; c++) acc[c] = fmaf(vv, sw[c * 9 + wi], acc[c]);
            }
        }
        float* dst = d_buf1 + (size_t)(b * 8) * HW + y * Ww + x;
        #pragma unroll
        for (int c = 0; c < 8; c++) dst[c * HW] = acc[c];
    }
    // partial stats (deterministic fixed tree); OOB threads contribute 0
    int lane = tid & 31, wid = tid >> 5;
    int blk = (blockIdx.z * TH + blockIdx.y) * TW + blockIdx.x;
    #pragma unroll
    for (int q = 0; q < 16; q++) {
        int c = q >> 1;
        float vv = (q & 1) ? acc[c] * acc[c] : acc[c];
        #pragma unroll
        for (int s = 16; s > 0; s >>= 1) vv += __shfl_down_sync(0xffffffffu, vv, s);
        if (lane == 0) wred[q * 8 + wid] = vv;
    }
    __syncthreads();
    if (tid < 16) {
        float s = 0.f;
        #pragma unroll
        for (int w = 0; w < 8; w++) s += wred[tid * 8 + w];
        d_part1[tid * NB1 + blk] = s;
    }
}

__global__ void k_stats1(const float* __restrict__ g, const float* __restrict__ be) {
    __shared__ float sums[16];
    int tid = threadIdx.x;                 // 128 threads
    int q = tid >> 3, l = tid & 7;
    float s = 0.f;
    #pragma unroll 4
    for (int i = l; i < NB1; i += 8) s += d_part1[q * NB1 + i];
    #pragma unroll
    for (int o = 4; o > 0; o >>= 1) s += __shfl_down_sync(0xffffffffu, s, o, 8);
    if (l == 0) sums[q] = s;
    __syncthreads();
    if (tid < 8) {
        float mean = sums[tid * 2] / (float)CNT;
        float var  = sums[tid * 2 + 1] / (float)CNT - mean * mean;
        float inv  = rsqrtf(var + BN_EPS);
        float sc   = g[tid] * inv;
        d_sc1[tid] = sc;
        d_sh1[tid] = be[tid] - mean * sc;
    }
}

// bn1+relu on load, tiled conv3x3 8->16 in smem, BN2 partial stats
__global__ __launch_bounds__(256) void k_conv2(const float* __restrict__ w2) {
    __shared__ float hs[8][18][20];
    __shared__ float sw[1152];
    __shared__ float ssc[8], ssh[8];
    __shared__ float wred[32 * 8];
    int b = blockIdx.z;
    int x0 = blockIdx.x * 16, y0 = blockIdx.y * 16;
    int tid = threadIdx.x;
    for (int i = tid; i < 1152; i += 256) sw[i] = w2[i];
    if (tid < 8) { ssc[tid] = d_sc1[tid]; ssh[tid] = d_sh1[tid]; }
    __syncthreads();
    const float* src = d_buf1 + (size_t)(b * 8) * HW;
    for (int i = tid; i < 8 * 18 * 18; i += 256) {
        int c = i / 324; int r = i - c * 324;
        int ly = r / 18, lx = r - ly * 18;
        int gy = y0 - 1 + ly, gx = x0 - 1 + lx;
        float v = 0.f;
        if (gy >= 0 && gy < Hh && gx >= 0 && gx < Ww) {
            v = fmaxf(fmaf(src[c * HW + gy * Ww + gx], ssc[c], ssh[c]), 0.f);
        }
        hs[c][ly][lx] = v;
    }
    __syncthreads();
    int ty = tid >> 4, tx = tid & 15;
    int y = y0 + ty, x = x0 + tx;
    float acc[16];
    #pragma unroll
    for (int i = 0; i < 16; i++) acc[i] = 0.f;
    bool in = (y < Hh && x < Ww);
    if (in) {
        #pragma unroll
        for (int ky = 0; ky < 3; ky++) {
            #pragma unroll
            for (int kx = 0; kx < 3; kx++) {
                int wi = ky * 3 + kx;
                #pragma unroll
                for (int ic = 0; ic < 8; ic++) {
                    float hv = hs[ic][ty + ky][tx + kx];
                    #pragma unroll
                    for (int oc = 0; oc < 16; oc++)
                        acc[oc] = fmaf(hv, sw[(oc * 8 + ic) * 9 + wi], acc[oc]);
                }
            }
        }
        float* dst = d_buf2 + (size_t)(b * 16) * HW + y * Ww + x;
        #pragma unroll
        for (int oc = 0; oc < 16; oc++) dst[oc * HW] = acc[oc];
    }
    int lane = tid & 31, wid = tid >> 5;
    int blk = (blockIdx.z * TH + blockIdx.y) * TW + blockIdx.x;
    #pragma unroll
    for (int q = 0; q < 32; q++) {
        int c = q >> 1;
        float v = (q & 1) ? acc[c] * acc[c] : acc[c];
        #pragma unroll
        for (int s = 16; s > 0; s >>= 1) v += __shfl_down_sync(0xffffffffu, v, s);
        if (lane == 0) wred[q * 8 + wid] = v;
    }
    __syncthreads();
    if (tid < 32) {
        float s = 0.f;
        #pragma unroll
        for (int w = 0; w < 8; w++) s += wred[tid * 8 + w];
        d_part2[tid * NB1 + blk] = s;
    }
}

__global__ void k_stats2(const float* __restrict__ g, const float* __restrict__ be) {
    __shared__ float sums[32];
    int tid = threadIdx.x;                 // 256 threads
    int q = tid >> 3, l = tid & 7;
    float s = 0.f;
    #pragma unroll 4
    for (int i = l; i < NB1; i += 8) s += d_part2[q * NB1 + i];
    #pragma unroll
    for (int o = 4; o > 0; o >>= 1) s += __shfl_down_sync(0xffffffffu, s, o, 8);
    if (l == 0) sums[q] = s;
    __syncthreads();
    if (tid < 16) {
        float mean = sums[tid * 2] / (float)CNT;
        float var  = sums[tid * 2 + 1] / (float)CNT - mean * mean;
        float inv  = rsqrtf(var + BN_EPS);
        float sc   = g[tid] * inv;
        d_sc2[tid] = sc;
        d_sh2[tid] = be[tid] - mean * sc;
    }
}

// single output writer: channels [0,384) passthrough copy, [384,400) bn2+relu
__global__ __launch_bounds__(256) void k_out(const float4* __restrict__ sp,
                                             float4* __restrict__ out) {
    constexpr int OUT4 = Bb * (C_IN + NDF) * PL4;   // 21,427,200
    constexpr int BP4  = (C_IN + NDF) * PL4;        // per-batch float4
    constexpr int SP4  = C_IN * PL4;                // spatial float4 per batch
    int stride = gridDim.x * blockDim.x;
    for (int i = blockIdx.x * blockDim.x + threadIdx.x; i < OUT4; i += stride) {
        int b = i / BP4;
        int rem = i - b * BP4;
        if (rem < SP4) {
            out[i] = sp[b * SP4 + rem];
        } else {
            int r = rem - SP4;
            int c = r / PL4;
            float4 v = reinterpret_cast<const float4*>(d_buf2)[b * NDF * PL4 + r];
            float sc = d_sc2[c], sh = d_sh2[c];
            v.x = fmaxf(fmaf(v.x, sc, sh), 0.f);
            v.y = fmaxf(fmaf(v.y, sc, sh), 0.f);
            v.z = fmaxf(fmaf(v.z, sc, sh), 0.f);
            v.w = fmaxf(fmaf(v.w, sc, sh), 0.f);
            out[i] = v;
        }
    }
}

// ---------------- launch ----------------
extern "C" void kernel_launch(void* const* d_in, const int* in_sizes, int n_in,
                              void* d_out, int out_size) {
    const float* spatial = (const float*)d_in[0];
    const float* points  = (const float*)d_in[1];
    const float* w1 = (const float*)d_in[2];
    const float* g1 = (const float*)d_in[3];
    const float* b1 = (const float*)d_in[4];
    const float* w2 = (const float*)d_in[5];
    const float* g2 = (const float*)d_in[6];
    const float* b2 = (const float*)d_in[7];
    float* out = (float*)d_out;
    int npts = in_sizes[1] / 5;

    k_init<<<512, 256>>>();
    k_hist<<<(npts + 255) / 256, 256>>>(points, npts);
    k_blur<<<dim3(14, 16, Bb), 256>>>();
    dim3 gt(TW, TH, Bb);
    k_resconv1<<<gt, 256>>>(w1);
    k_stats1<<<1, 128>>>(g1, b1);
    k_conv2<<<gt, 256>>>(w2);
    k_stats2<<<1, 256>>>(g2, b2);
    constexpr int OUT4 = Bb * (C_IN + NDF) * PL4;
    int nblk = min((OUT4 + 255) / 256, 148 * 16);
    k_out<<<nblk, 256>>>((const float4*)spatial, (float4*)out);
}